// round 9
// baseline (speedup 1.0000x reference)
#include <cuda_runtime.h>

#define OUT_DIM 8192
#define IN_DIM  8192
#define BATCH   32
// reference: new_w = clip(w + LR * (sum_b post*pre)/B, 0, 1), LR=0.01, B=32
#define LRB (0.01f / 32.0f)

// Packed dual-FMA on two f32 lanes (FFMA2, PTX-only form): d = a*b + d
static __device__ __forceinline__ void ffma2(unsigned long long &d,
                                             unsigned long long a,
                                             unsigned long long b) {
    asm("fma.rn.f32x2 %0, %1, %2, %3;" : "=l"(d) : "l"(a), "l"(b), "l"(d));
}

// CTA tile: 32 (o) x 256 (i), 256 threads = 8 warps.
//   warp -> iw = warp&1 (i half: 128 floats), ow = warp>>1 (o octet: 8 rows)
// Thread tile: 8 (o) x 4 (i) as 2 f32x2 pairs; lane owns i = i0+iw*128+4*lane.
__global__ __launch_bounds__(256) void stdp_fused_kernel(
    const float* __restrict__ W,
    const float* __restrict__ pre,
    const float* __restrict__ post,
    float* __restrict__ Wout)
{
    __shared__ float  pre_s[BATCH][256];    // 32 KB, i-contiguous per b
    __shared__ float2 postd_s[BATCH][32];   //  8 KB, {p,p} duplicated for f32x2

    const int t    = threadIdx.x;
    const int lane = t & 31;
    const int warp = t >> 5;
    const int iw   = warp & 1;
    const int ow   = warp >> 1;
    const int o0   = blockIdx.y * 32;
    const int i0   = blockIdx.x * 256;

    // --- stage pre tile [32 b][256 i] via float4 (coalesced) ---
    for (int idx = t; idx < BATCH * 64; idx += 256) {
        int b = idx >> 6;
        int j = idx & 63;
        float4 v = *(const float4*)(pre + (size_t)b * IN_DIM + i0 + j * 4);
        *(float4*)&pre_s[b][j * 4] = v;
    }
    // --- stage post tile duplicated: postd_s[b][o'] = {post[b,o0+o'], same} ---
    for (int idx = t; idx < BATCH * 32; idx += 256) {
        int b = idx >> 5;
        int o = idx & 31;
        float v = post[(size_t)b * OUT_DIM + o0 + o];
        postd_s[b][o] = make_float2(v, v);
    }
    __syncthreads();

    unsigned long long acc[8][2];  // [o-row][i-pair]; each = two f32 accumulators
#pragma unroll
    for (int r = 0; r < 8; ++r) {
        acc[r][0] = 0ULL;
        acc[r][1] = 0ULL;
    }

    const float* preq  = &pre_s[0][iw * 128 + 4 * lane];   // 16B-aligned
    const float2* postp = &postd_s[0][ow * 8];

#pragma unroll 8
    for (int b = 0; b < BATCH; ++b) {
        // pre: one LDS.128 -> two f32x2 pairs (i, i+1) and (i+2, i+3)
        ulonglong2 qq = *(const ulonglong2*)(preq + (size_t)b * 256);
        // post: 4x LDS.128 broadcast, interleaved with FFMA2 to cap reg pressure
#pragma unroll
        for (int g = 0; g < 4; ++g) {
            ulonglong2 pp = *(const ulonglong2*)((const float*)postp + (size_t)b * 64 + 4 * g);
            ffma2(acc[2 * g][0],     pp.x, qq.x);
            ffma2(acc[2 * g][1],     pp.x, qq.y);
            ffma2(acc[2 * g + 1][0], pp.y, qq.x);
            ffma2(acc[2 * g + 1][1], pp.y, qq.y);
        }
    }

    // --- fused epilogue: w + (LR/B)*delta, clip [0,1], float4 coalesced ---
    const size_t ibase = (size_t)(i0 + iw * 128 + 4 * lane);
#pragma unroll
    for (int r = 0; r < 8; ++r) {
        size_t o = (size_t)(o0 + ow * 8 + r);
        const float4* wp = (const float4*)(W    + o * IN_DIM + ibase);
        float4*       op = (float4*)      (Wout + o * IN_DIM + ibase);
        float4 wv = *wp;
        float2 d0 = *(float2*)&acc[r][0];
        float2 d1 = *(float2*)&acc[r][1];
        float4 res;
        res.x = fminf(fmaxf(fmaf(d0.x, LRB, wv.x), 0.0f), 1.0f);
        res.y = fminf(fmaxf(fmaf(d0.y, LRB, wv.y), 0.0f), 1.0f);
        res.z = fminf(fmaxf(fmaf(d1.x, LRB, wv.z), 0.0f), 1.0f);
        res.w = fminf(fmaxf(fmaf(d1.y, LRB, wv.w), 0.0f), 1.0f);
        *op = res;
    }
}

extern "C" void kernel_launch(void* const* d_in, const int* in_sizes, int n_in,
                              void* d_out, int out_size) {
    const float* W    = (const float*)d_in[0];  // weights [8192, 8192]
    const float* pre  = (const float*)d_in[1];  // pre_activity [32, 8192]
    const float* post = (const float*)d_in[2];  // post_activity [32, 8192]
    float* out = (float*)d_out;                 // [8192, 8192]

    dim3 grid(IN_DIM / 256, OUT_DIM / 32);      // (32, 256)
    stdp_fused_kernel<<<grid, 256>>>(W, pre, post, out);
}

// round 16
// speedup vs baseline: 1.0415x; 1.0415x over previous
#include <cuda_runtime.h>

#define OUT_DIM 8192
#define IN_DIM  8192
#define BATCH   32
// reference: new_w = clip(w + LR * (sum_b post*pre)/B, 0, 1), LR=0.01, B=32
#define LRB (0.01f / 32.0f)

// Packed dual-FMA on two f32 lanes (FFMA2, PTX-only form): d = a*b + d
static __device__ __forceinline__ void ffma2(unsigned long long &d,
                                             unsigned long long a,
                                             unsigned long long b) {
    asm("fma.rn.f32x2 %0, %1, %2, %3;" : "=l"(d) : "l"(a), "l"(b), "l"(d));
}

// CTA tile: 32 (o) x 256 (i), 256 threads = 8 warps.
//   warp -> iw = warp&1 (which 128-float i half), ow = warp>>1 (8-row o octet)
// Thread tile: 8 (o) x 4 (i) as 2 f32x2 pairs; lane owns i = i0+iw*128+4*lane.
// Per warp per b: 1 LDS.128 pre (4 cyc) + 4 broadcast LDS.128 post (4 cyc)
// feeding 16 FFMA2 per thread -> 128 FMA per crossbar cycle (optimum at rc=16).
__global__ __launch_bounds__(256, 4) void stdp_fused_kernel(
    const float* __restrict__ W,
    const float* __restrict__ pre,
    const float* __restrict__ post,
    float* __restrict__ Wout)
{
    __shared__ float  pre_s[BATCH][256];    // 32 KB, i-contiguous per b
    __shared__ float2 postd_s[BATCH][32];   //  8 KB, {p,p} duplicated for f32x2

    const int t    = threadIdx.x;
    const int lane = t & 31;
    const int warp = t >> 5;
    const int iw   = warp & 1;
    const int ow   = warp >> 1;
    const int o0   = blockIdx.y * 32;
    const int i0   = blockIdx.x * 256;

    // --- stage pre tile [32 b][256 i] via float4 (coalesced) ---
    for (int idx = t; idx < BATCH * 64; idx += 256) {
        int b = idx >> 6;
        int j = idx & 63;
        float4 v = *(const float4*)(pre + (size_t)b * IN_DIM + i0 + j * 4);
        *(float4*)&pre_s[b][j * 4] = v;
    }
    // --- stage post tile duplicated: postd_s[b][o'] = {post[b,o0+o'], same} ---
    for (int idx = t; idx < BATCH * 32; idx += 256) {
        int b = idx >> 5;
        int o = idx & 31;
        float v = post[(size_t)b * OUT_DIM + o0 + o];
        postd_s[b][o] = make_float2(v, v);
    }
    __syncthreads();

    unsigned long long acc[8][2];  // [o-row][i-pair]; 32 regs total
#pragma unroll
    for (int r = 0; r < 8; ++r) {
        acc[r][0] = 0ULL;
        acc[r][1] = 0ULL;
    }

    const float* preq  = &pre_s[0][iw * 128 + 4 * lane];   // 16B aligned
    const float* postp = (const float*)&postd_s[0][ow * 8];

    // Double-buffered pre: prefetch b+1 while FFMA2s consume b, hiding the
    // 29-cyc LDS latency behind the 16-FFMA2 body.
    ulonglong2 qq = *(const ulonglong2*)preq;
#pragma unroll 8
    for (int b = 0; b < BATCH; ++b) {
        ulonglong2 qn;
        if (b < BATCH - 1)
            qn = *(const ulonglong2*)(preq + (size_t)(b + 1) * 256);
#pragma unroll
        for (int g = 0; g < 4; ++g) {
            // broadcast LDS.128: two duplicated post pairs (2 o-rows)
            ulonglong2 pp = *(const ulonglong2*)(postp + (size_t)b * 64 + 4 * g);
            ffma2(acc[2 * g][0],     pp.x, qq.x);
            ffma2(acc[2 * g][1],     pp.x, qq.y);
            ffma2(acc[2 * g + 1][0], pp.y, qq.x);
            ffma2(acc[2 * g + 1][1], pp.y, qq.y);
        }
        qq = qn;
    }

    // --- fused epilogue: w + (LR/B)*delta, clip [0,1], float4 coalesced ---
    const size_t ibase = (size_t)(i0 + iw * 128 + 4 * lane);
#pragma unroll
    for (int r = 0; r < 8; ++r) {
        size_t o = (size_t)(o0 + ow * 8 + r);
        const float4* wp = (const float4*)(W    + o * IN_DIM + ibase);
        float4*       op = (float4*)      (Wout + o * IN_DIM + ibase);
        float4 wv = *wp;
        float2 d0 = *(float2*)&acc[r][0];
        float2 d1 = *(float2*)&acc[r][1];
        float4 res;
        res.x = fminf(fmaxf(fmaf(d0.x, LRB, wv.x), 0.0f), 1.0f);
        res.y = fminf(fmaxf(fmaf(d0.y, LRB, wv.y), 0.0f), 1.0f);
        res.z = fminf(fmaxf(fmaf(d1.x, LRB, wv.z), 0.0f), 1.0f);
        res.w = fminf(fmaxf(fmaf(d1.y, LRB, wv.w), 0.0f), 1.0f);
        *op = res;
    }
}

extern "C" void kernel_launch(void* const* d_in, const int* in_sizes, int n_in,
                              void* d_out, int out_size) {
    const float* W    = (const float*)d_in[0];  // weights [8192, 8192]
    const float* pre  = (const float*)d_in[1];  // pre_activity [32, 8192]
    const float* post = (const float*)d_in[2];  // post_activity [32, 8192]
    float* out = (float*)d_out;                 // [8192, 8192]

    dim3 grid(IN_DIM / 256, OUT_DIM / 32);      // (32, 256)
    stdp_fused_kernel<<<grid, 256>>>(W, pre, post, out);
}

// round 17
// speedup vs baseline: 1.1390x; 1.0937x over previous
#include <cuda_runtime.h>

#define OUT_DIM 8192
#define IN_DIM  8192
#define BATCH   32
// reference: new_w = clip(w + LR * (sum_b post*pre)/B, 0, 1), LR=0.01, B=32
#define LRB (0.01f / 32.0f)

// Packed dual-FMA on two f32 lanes (FFMA2, PTX-only form): d = a*b + d
static __device__ __forceinline__ void ffma2(unsigned long long &d,
                                             unsigned long long a,
                                             unsigned long long b) {
    asm("fma.rn.f32x2 %0, %1, %2, %3;" : "=l"(d) : "l"(a), "l"(b), "l"(d));
}
// Duplicate one f32 into both lanes of a packed f32x2
static __device__ __forceinline__ unsigned long long dup2(float p) {
    unsigned long long d;
    asm("mov.b64 %0, {%1, %1};" : "=l"(d) : "f"(p));
    return d;
}

// CTA tile: 32 (o) x 256 (i), 256 threads = 8 warps.
//   warp -> iw = warp&1 (which 128-float i half), ow = warp>>1 (8-row o octet)
// Thread tile: 8 (o) x 4 (i) as 2 f32x2 pairs; lane owns i = i0+iw*128+4*lane.
// Inner loop L1 traffic: ONE LDS.128 per warp per b (pre). post comes from
// registers via __shfl_sync (lane L holds post[b=L][warp's 8 o-rows]).
__global__ __launch_bounds__(256, 4) void stdp_fused_kernel(
    const float* __restrict__ W,
    const float* __restrict__ pre,
    const float* __restrict__ post,
    float* __restrict__ Wout)
{
    __shared__ float pre_s[BATCH][256];    // 32 KB, i-contiguous per b
    __shared__ float post_s[BATCH][33];    // 4.2 KB, padded: conflict-free col reads

    const int t    = threadIdx.x;
    const int lane = t & 31;
    const int warp = t >> 5;
    const int iw   = warp & 1;
    const int ow   = warp >> 1;
    const int o0   = blockIdx.y * 32;
    const int i0   = blockIdx.x * 256;

    // --- stage pre tile [32 b][256 i] via float4 (coalesced) ---
    for (int idx = t; idx < BATCH * 64; idx += 256) {
        int b = idx >> 6;
        int j = idx & 63;
        float4 v = *(const float4*)(pre + (size_t)b * IN_DIM + i0 + j * 4);
        *(float4*)&pre_s[b][j * 4] = v;
    }
    // --- stage post tile [32 b][32 o'] (coalesced, padded rows) ---
    for (int idx = t; idx < BATCH * 32; idx += 256) {
        int b = idx >> 5;
        int o = idx & 31;
        post_s[b][o] = post[(size_t)b * OUT_DIM + o0 + o];
    }
    __syncthreads();

    // --- pull post into registers: lane L owns batch b=L, warp's 8 o-rows ---
    // addr/4 = lane*33 + ow*8 + r  -> banks distinct across lanes (33 coprime 32)
    float pr[8];
#pragma unroll
    for (int r = 0; r < 8; ++r)
        pr[r] = post_s[lane][ow * 8 + r];

    unsigned long long acc[8][2];  // [o-row][i-pair]; 32 regs total
#pragma unroll
    for (int r = 0; r < 8; ++r) {
        acc[r][0] = 0ULL;
        acc[r][1] = 0ULL;
    }

    const float* preq = &pre_s[0][iw * 128 + 4 * lane];   // 16B aligned

    // Double-buffered pre: prefetch b+1 while FFMA2s consume b.
    ulonglong2 qq = *(const ulonglong2*)preq;
#pragma unroll 4
    for (int b = 0; b < BATCH; ++b) {
        ulonglong2 qn;
        if (b < BATCH - 1)
            qn = *(const ulonglong2*)(preq + (size_t)(b + 1) * 256);
#pragma unroll
        for (int r = 0; r < 8; ++r) {
            // broadcast post[b][o-row r] from lane b (MIO shuffle, no L1TEX)
            unsigned long long pp = dup2(__shfl_sync(0xffffffffu, pr[r], b));
            ffma2(acc[r][0], pp, qq.x);
            ffma2(acc[r][1], pp, qq.y);
        }
        qq = qn;
    }

    // --- fused epilogue: w + (LR/B)*delta, clip [0,1], float4 coalesced ---
    const size_t ibase = (size_t)(i0 + iw * 128 + 4 * lane);
#pragma unroll
    for (int r = 0; r < 8; ++r) {
        size_t o = (size_t)(o0 + ow * 8 + r);
        const float4* wp = (const float4*)(W    + o * IN_DIM + ibase);
        float4*       op = (float4*)      (Wout + o * IN_DIM + ibase);
        float4 wv = *wp;
        float2 d0 = *(float2*)&acc[r][0];
        float2 d1 = *(float2*)&acc[r][1];
        float4 res;
        res.x = fminf(fmaxf(fmaf(d0.x, LRB, wv.x), 0.0f), 1.0f);
        res.y = fminf(fmaxf(fmaf(d0.y, LRB, wv.y), 0.0f), 1.0f);
        res.z = fminf(fmaxf(fmaf(d1.x, LRB, wv.z), 0.0f), 1.0f);
        res.w = fminf(fmaxf(fmaf(d1.y, LRB, wv.w), 0.0f), 1.0f);
        *op = res;
    }
}

extern "C" void kernel_launch(void* const* d_in, const int* in_sizes, int n_in,
                              void* d_out, int out_size) {
    const float* W    = (const float*)d_in[0];  // weights [8192, 8192]
    const float* pre  = (const float*)d_in[1];  // pre_activity [32, 8192]
    const float* post = (const float*)d_in[2];  // post_activity [32, 8192]
    float* out = (float*)d_out;                 // [8192, 8192]

    dim3 grid(IN_DIM / 256, OUT_DIM / 32);      // (32, 256)
    stdp_fused_kernel<<<grid, 256>>>(W, pre, post, out);
}